// round 17
// baseline (speedup 1.0000x reference)
#include <cuda_runtime.h>
#include <math.h>

// NeighborSearch: fixed-radius search, CSR float32 output [indices | splits].
// Exact fp semantics (pinned R14, rel_err=0.0 since R15):
//   n(p) = (x*x + z*z) + y*y
//   dot  = fma(qz,dz, fma(qy,dy, qx*dx))
//   sq   = fma(-2, dot, rn(nq + nd));  hit = sq <= T
//   T    = largest f32 with sqrt_rn(T) <= radius
// R17: 12^3 cell grid culls pair tests 64x (conservative geometric cull;
// accepted pairs use identical fp ops). Shuffle-based scans (R16 ncu: old
// scan burned 28.8us at issue=3.2%).

#define MAXN    16384
#define G       12
#define NCELLS  (G * G * G)
#define BUFCAP  192
#define QBLK    256

__device__ float  g_T;
__device__ float  g_R;
__device__ int    g_cellcnt[NCELLS];
__device__ int    g_cellstart[NCELLS];
__device__ int    g_cellcur[NCELLS];
__device__ float4 g_pts[MAXN];      // x,y,z,norm (grid-sorted)
__device__ int    g_pidx[MAXN];     // original index (grid-sorted)
__device__ int    g_qtot[MAXN];
__device__ int    g_offsets[MAXN + 1];
__device__ int    g_stage[MAXN * BUFCAP];

// ------------------------------------------------------------- thresh -----
__global__ void thresh_kernel(const float* __restrict__ radius_ptr) {
    float r = 0.08f;
    if (radius_ptr != nullptr) {
        float f = *radius_ptr;
        if (f > 1e-6f && f < 1e3f) r = f;
    }
    g_R = r;
    float t = __fmul_rn(r, r);
    if (__fsqrt_rn(t) <= r) {
        for (int it = 0; it < 64; ++it) {
            float nt = nextafterf(t, 3.402823466e38f);
            if (__fsqrt_rn(nt) <= r) t = nt; else break;
        }
    } else {
        for (int it = 0; it < 64 && __fsqrt_rn(t) > r; ++it)
            t = nextafterf(t, 0.0f);
    }
    g_T = t;
}

__global__ void zero_kernel() {
    int i = blockIdx.x * blockDim.x + threadIdx.x;
    if (i < NCELLS) g_cellcnt[i] = 0;
}

__device__ __forceinline__ float norm_ox(float x, float y, float z) {
    return __fadd_rn(__fadd_rn(__fmul_rn(x, x), __fmul_rn(z, z)),
                     __fmul_rn(y, y));
}

__device__ __forceinline__ float pair_sq(float qx, float qy, float qz, float qn,
                                         float4 d) {
    float dot = __fmaf_rn(qz, d.z, __fmaf_rn(qy, d.y, __fmul_rn(qx, d.x)));
    return __fmaf_rn(-2.0f, dot, __fadd_rn(qn, d.w));
}

__device__ __forceinline__ int cell_of(float x, float y, float z) {
    int ix = min(G - 1, max(0, (int)(x * G)));
    int iy = min(G - 1, max(0, (int)(y * G)));
    int iz = min(G - 1, max(0, (int)(z * G)));
    return (ix * G + iy) * G + iz;
}

// ------------------------------------------------------------ grid build --
__global__ void cellcount_kernel(const float* __restrict__ data, int nd) {
    int i = blockIdx.x * blockDim.x + threadIdx.x;
    if (i >= nd) return;
    atomicAdd(&g_cellcnt[cell_of(data[3*i], data[3*i+1], data[3*i+2])], 1);
}

// exclusive block scan over 512 threads (shuffle + 16 warp sums, 2 barriers)
__device__ __forceinline__ int block_exscan_512(int mysum) {
    __shared__ int wsum[16];
    const int lane = threadIdx.x & 31;
    const int wid  = threadIdx.x >> 5;
    int inc = mysum;
#pragma unroll
    for (int d = 1; d < 32; d <<= 1) {
        int v = __shfl_up_sync(0xffffffffu, inc, d);
        if (lane >= d) inc += v;
    }
    if (lane == 31) wsum[wid] = inc;
    __syncthreads();
    if (wid == 0 && lane < 16) {
        int w = wsum[lane];
#pragma unroll
        for (int d = 1; d < 16; d <<= 1) {
            int v = __shfl_up_sync(0xffffu, w, d);
            if (lane >= d) w += v;
        }
        wsum[lane] = w;
    }
    __syncthreads();
    int wpre = (wid == 0) ? 0 : wsum[wid - 1];
    return wpre + inc - mysum;
}

__global__ void cellscan_kernel() {
    const int tid = threadIdx.x;
    const int PER = (NCELLS + 511) / 512;   // 4
    int v[PER], mysum = 0;
#pragma unroll
    for (int i = 0; i < PER; ++i) {
        int c = tid * PER + i;
        v[i] = (c < NCELLS) ? g_cellcnt[c] : 0;
        mysum += v[i];
    }
    int run = block_exscan_512(mysum);
#pragma unroll
    for (int i = 0; i < PER; ++i) {
        int c = tid * PER + i;
        if (c < NCELLS) { g_cellstart[c] = run; g_cellcur[c] = run; run += v[i]; }
    }
}

__global__ void scatter_kernel(const float* __restrict__ data, int nd) {
    int i = blockIdx.x * blockDim.x + threadIdx.x;
    if (i >= nd) return;
    float x = data[3*i], y = data[3*i+1], z = data[3*i+2];
    int slot = atomicAdd(&g_cellcur[cell_of(x, y, z)], 1);
    g_pts[slot]  = make_float4(x, y, z, norm_ox(x, y, z));
    g_pidx[slot] = i;
}

// ---------------------------------------------------------------- query ---
__global__ void query_kernel(const float* __restrict__ queries, int nq) {
    int q = blockIdx.x * blockDim.x + threadIdx.x;
    if (q >= nq) return;

    float qx = queries[3*q], qy = queries[3*q+1], qz = queries[3*q+2];
    float qn = norm_ox(qx, qy, qz);
    const float T = g_T;
    const float r = g_R * 1.0001f;

    int ix0 = max(0, (int)floorf((qx - r) * G));
    int ix1 = min(G - 1, (int)floorf((qx + r) * G));
    int iy0 = max(0, (int)floorf((qy - r) * G));
    int iy1 = min(G - 1, (int)floorf((qy + r) * G));
    int iz0 = max(0, (int)floorf((qz - r) * G));
    int iz1 = min(G - 1, (int)floorf((qz + r) * G));

    int buf[BUFCAP];
    int cnt = 0;
    for (int ix = ix0; ix <= ix1; ++ix)
        for (int iy = iy0; iy <= iy1; ++iy)
            for (int iz = iz0; iz <= iz1; ++iz) {
                int cell = (ix * G + iy) * G + iz;
                int s = g_cellstart[cell];
                int e = s + g_cellcnt[cell];
                for (int k = s; k < e; ++k) {
                    if (pair_sq(qx, qy, qz, qn, g_pts[k]) <= T) {
                        if (cnt < BUFCAP) buf[cnt] = g_pidx[k];
                        ++cnt;
                    }
                }
            }
    g_qtot[q] = cnt;

    int m = min(cnt, BUFCAP);
    for (int k = 1; k < m; ++k) {          // insertion sort ascending
        int v = buf[k], j = k - 1;
        while (j >= 0 && buf[j] > v) { buf[j + 1] = buf[j]; --j; }
        buf[j + 1] = v;
    }
    for (int t = 0; t < m; ++t) g_stage[q * BUFCAP + t] = buf[t];
}

// ---------------------------------------------------------------- scan ----
__global__ void scan_kernel(float* __restrict__ splits, int nq, int has_splits) {
    const int tid = threadIdx.x;
    const int PER = (MAXN + 511) / 512;    // 32
    int v[PER], mysum = 0;
#pragma unroll
    for (int i = 0; i < PER; ++i) {
        int q = tid * PER + i;
        v[i] = (q < nq) ? g_qtot[q] : 0;
        mysum += v[i];
    }
    int run = block_exscan_512(mysum);
#pragma unroll
    for (int i = 0; i < PER; ++i) {
        int q = tid * PER + i;
        if (q < nq) {
            g_offsets[q] = run;
            if (has_splits) splits[q] = (float)run;
            run += v[i];
        }
        if (q == nq) {
            g_offsets[nq] = run;
            if (has_splits) splits[nq] = (float)run;
        }
    }
    if (tid == 511) {   // nq == MAXN case: tail boundary
        if (511 * PER + PER == nq) {
            g_offsets[nq] = run;
            if (has_splits) splits[nq] = (float)run;
        }
    }
}

// ---------------------------------------------------------------- emit ----
__global__ void emit_kernel(int nq, float* __restrict__ out, int cap) {
    int q = blockIdx.x * blockDim.x + threadIdx.x;
    if (q >= nq) return;
    int off = g_offsets[q];
    int cnt = min(g_qtot[q], BUFCAP);
    for (int t = 0; t < cnt; ++t) {
        int w = off + t;
        if (w >= 0 && w < cap) out[w] = (float)g_stage[q * BUFCAP + t];
    }
}

// -------------------------------------------------------------- launch ----
extern "C" void kernel_launch(void* const* d_in, const int* in_sizes, int n_in,
                              void* d_out, int out_size) {
    const float* data    = (const float*)d_in[0];
    const float* queries = (const float*)d_in[1];
    const float* radius  = (n_in >= 3 && in_sizes[2] >= 1) ? (const float*)d_in[2]
                                                           : nullptr;
    const int nd = in_sizes[0] / 3;
    const int nq = in_sizes[1] / 3;
    if (nd <= 0 || nq <= 0 || nd > MAXN || nq > MAXN) return;

    float* out = (float*)d_out;
    const int has_splits = (out_size >= nq + 1) ? 1 : 0;
    float* splits = has_splits ? (out + (out_size - (nq + 1))) : out;
    const int cap = has_splits ? (out_size - (nq + 1)) : out_size;

    const int dblocks = (nd + QBLK - 1) / QBLK;
    const int qblocks = (nq + QBLK - 1) / QBLK;

    thresh_kernel   <<<1, 1>>>(radius);
    zero_kernel     <<<(NCELLS + QBLK - 1) / QBLK, QBLK>>>();
    cellcount_kernel<<<dblocks, QBLK>>>(data, nd);
    cellscan_kernel <<<1, 512>>>();
    scatter_kernel  <<<dblocks, QBLK>>>(data, nd);
    query_kernel    <<<qblocks, QBLK>>>(queries, nq);
    scan_kernel     <<<1, 512>>>(splits, nq, has_splits);
    emit_kernel     <<<qblocks, QBLK>>>(nq, out, cap);
}